// round 2
// baseline (speedup 1.0000x reference)
#include <cuda_runtime.h>
#include <cuda_bf16.h>
#include <math.h>

#define N_NODES 50000
#define EDGES   800000
#define ET      (EDGES + N_NODES)   // edges + self loops = 850000
#define NHEAD   8
#define DH      32
#define FDIM    256

// ---------------- scratch (device globals; no allocation allowed) ------------
__device__ float g_h0[N_NODES * FDIM];
__device__ float g_h[N_NODES * FDIM];
__device__ float g_hp[N_NODES * FDIM];
__device__ float g_outacc[N_NODES * FDIM];
__device__ float g_embs[3 * N_NODES * FDIM];
__device__ float g_ssrc[N_NODES * NHEAD];
__device__ float g_sdst[N_NODES * NHEAD];
__device__ unsigned g_maxbuf[N_NODES * NHEAD];
__device__ float g_denom[N_NODES * NHEAD];
__device__ float g_hsem[3 * N_NODES * 128];
__device__ float g_z[N_NODES * FDIM];
__device__ float g_hcls[N_NODES * 128];

// ---------------- helpers ----------------------------------------------------
__device__ __forceinline__ unsigned enc_f(float f) {
    unsigned u = __float_as_uint(f);
    return (u & 0x80000000u) ? ~u : (u | 0x80000000u);
}
__device__ __forceinline__ float dec_f(unsigned e) {
    return __uint_as_float((e & 0x80000000u) ? (e ^ 0x80000000u) : ~e);
}
__device__ __forceinline__ void edge_sd(const int* __restrict__ srcs,
                                        const int* __restrict__ dsts,
                                        int eid, int& s, int& d) {
    if (eid < EDGES) { s = srcs[eid]; d = dsts[eid]; }
    else             { s = eid - EDGES; d = s; }
}

// ---------------- GEMM: C[M,Nc] = A[M,K] @ B[K,Nc] (+bias)(+relu) ------------
// 64x64 tile, BK=16, 256 threads, 4x4 microtile.
template <int EPI>  // 0 = none, 1 = +bias, 2 = +bias, relu
__global__ void __launch_bounds__(256)
gemm_kernel(const float* __restrict__ A, const float* __restrict__ B,
            const float* __restrict__ bias, float* __restrict__ C,
            int M, int K, int Nc) {
    __shared__ float As[16][64];
    __shared__ float Bs[16][64];
    const int bm = blockIdx.x * 64;
    const int bn = blockIdx.y * 64;
    const int tid = threadIdx.x;
    const int tx = tid & 15, ty = tid >> 4;

    float acc[4][4];
#pragma unroll
    for (int i = 0; i < 4; i++)
#pragma unroll
        for (int j = 0; j < 4; j++) acc[i][j] = 0.f;

    for (int k0 = 0; k0 < K; k0 += 16) {
#pragma unroll
        for (int i = 0; i < 4; i++) {
            int e = tid + i * 256;
            int m = e >> 4, k = e & 15;
            int gm = bm + m;
            As[k][m] = (gm < M) ? A[(size_t)gm * K + k0 + k] : 0.f;
        }
#pragma unroll
        for (int i = 0; i < 4; i++) {
            int e = tid + i * 256;
            int k = e >> 6, n = e & 63;
            Bs[k][n] = B[(size_t)(k0 + k) * Nc + bn + n];
        }
        __syncthreads();
#pragma unroll
        for (int k = 0; k < 16; k++) {
            float a[4], b[4];
#pragma unroll
            for (int i = 0; i < 4; i++) a[i] = As[k][ty * 4 + i];
#pragma unroll
            for (int j = 0; j < 4; j++) b[j] = Bs[k][tx * 4 + j];
#pragma unroll
            for (int i = 0; i < 4; i++)
#pragma unroll
                for (int j = 0; j < 4; j++) acc[i][j] = fmaf(a[i], b[j], acc[i][j]);
        }
        __syncthreads();
    }
#pragma unroll
    for (int i = 0; i < 4; i++) {
        int m = bm + ty * 4 + i;
        if (m >= M) continue;
#pragma unroll
        for (int j = 0; j < 4; j++) {
            int n = bn + tx * 4 + j;
            float v = acc[i][j];
            if (EPI >= 1) v += bias[n];
            if (EPI == 2) v = fmaxf(v, 0.f);
            C[(size_t)m * Nc + n] = v;
        }
    }
}

// -------- per-(node,head) attention logits -----------------------------------
__global__ void scores_kernel(const float* __restrict__ hp,
                              const float* __restrict__ asrc,
                              const float* __restrict__ adst) {
    int idx = blockIdx.x * blockDim.x + threadIdx.x;
    if (idx >= N_NODES * NHEAD) return;
    int n = idx >> 3, h = idx & 7;
    const float4* v = (const float4*)(hp + (size_t)n * FDIM + h * DH);
    const float4* a = (const float4*)(asrc + h * DH);
    const float4* b = (const float4*)(adst + h * DH);
    float s1 = 0.f, s2 = 0.f;
#pragma unroll
    for (int i = 0; i < 8; i++) {
        float4 x = v[i], p = a[i], q = b[i];
        s1 += x.x * p.x + x.y * p.y + x.z * p.z + x.w * p.w;
        s2 += x.x * q.x + x.y * q.y + x.z * q.z + x.w * q.w;
    }
    g_ssrc[idx] = s1;
    g_sdst[idx] = s2;
}

__global__ void init_kernel() {
    int idx = blockIdx.x * blockDim.x + threadIdx.x;
    if (idx < N_NODES * FDIM) g_outacc[idx] = 0.f;
    if (idx < N_NODES * NHEAD) { g_maxbuf[idx] = 0u; g_denom[idx] = 0.f; }
}

__global__ void passA_kernel(const int* __restrict__ srcs, const int* __restrict__ dsts) {
    int idx = blockIdx.x * blockDim.x + threadIdx.x;
    if (idx >= ET * NHEAD) return;
    int eid = idx >> 3, h = idx & 7;
    int s, d; edge_sd(srcs, dsts, eid, s, d);
    float v = g_ssrc[s * NHEAD + h] + g_sdst[d * NHEAD + h];
    v = v > 0.f ? v : 0.2f * v;
    atomicMax(&g_maxbuf[d * NHEAD + h], enc_f(v));
}

__global__ void passB_kernel(const int* __restrict__ srcs, const int* __restrict__ dsts) {
    int idx = blockIdx.x * blockDim.x + threadIdx.x;
    if (idx >= ET * NHEAD) return;
    int eid = idx >> 3, h = idx & 7;
    int s, d; edge_sd(srcs, dsts, eid, s, d);
    float v = g_ssrc[s * NHEAD + h] + g_sdst[d * NHEAD + h];
    v = v > 0.f ? v : 0.2f * v;
    float m = dec_f(g_maxbuf[d * NHEAD + h]);
    atomicAdd(&g_denom[d * NHEAD + h], expf(v - m));
}

// one 64-thread group per edge (4 edges per 256-thread block);
// each thread handles 4 contiguous floats -> float4 vector RED.
__global__ void __launch_bounds__(256)
passC_kernel(const int* __restrict__ srcs, const int* __restrict__ dsts) {
    int eid = blockIdx.x * 4 + (threadIdx.x >> 6);
    if (eid >= ET) return;
    int t = threadIdx.x & 63;
    int s, d; edge_sd(srcs, dsts, eid, s, d);
    int h = t >> 3;
    float v = g_ssrc[s * NHEAD + h] + g_sdst[d * NHEAD + h];
    v = v > 0.f ? v : 0.2f * v;
    float m = dec_f(g_maxbuf[d * NHEAD + h]);
    float alpha = expf(v - m) / g_denom[d * NHEAD + h];
    const float4* hp4 = (const float4*)(g_hp + (size_t)s * FDIM);
    float4 x = hp4[t];
    float4 c = make_float4(alpha * x.x, alpha * x.y, alpha * x.z, alpha * x.w);
    atomicAdd(((float4*)(g_outacc + (size_t)d * FDIM)) + t, c);
}

__global__ void epilogue_kernel(const float* __restrict__ bias, float* __restrict__ hnext) {
    int idx = blockIdx.x * blockDim.x + threadIdx.x;
    if (idx >= N_NODES * FDIM) return;
    float v = g_outacc[idx] + bias[idx & 255];
    hnext[idx] = v > 0.f ? v : expm1f(v);
}

// -------- semantic attention fuse: scores -> softmax -> weighted sum ---------
__global__ void __launch_bounds__(128)
semfuse_kernel(const float* __restrict__ semW2) {
    int n = blockIdx.x;
    int t = threadIdx.x;  // 128
    __shared__ float red[4];
    __shared__ float w[3];
    float sloc[3];
    for (int p = 0; p < 3; p++) {
        float v = tanhf(g_hsem[((size_t)p * N_NODES + n) * 128 + t]) * semW2[t];
#pragma unroll
        for (int o = 16; o; o >>= 1) v += __shfl_down_sync(0xffffffffu, v, o);
        if ((t & 31) == 0) red[t >> 5] = v;
        __syncthreads();
        if (t == 0) sloc[p] = red[0] + red[1] + red[2] + red[3];
        __syncthreads();
    }
    if (t == 0) {
        float mx = fmaxf(sloc[0], fmaxf(sloc[1], sloc[2]));
        float e0 = expf(sloc[0] - mx), e1 = expf(sloc[1] - mx), e2 = expf(sloc[2] - mx);
        float inv = 1.f / (e0 + e1 + e2);
        w[0] = e0 * inv; w[1] = e1 * inv; w[2] = e2 * inv;
    }
    __syncthreads();
    for (int c = t; c < FDIM; c += 128) {
        float acc = 0.f;
#pragma unroll
        for (int p = 0; p < 3; p++)
            acc += w[p] * g_embs[((size_t)p * N_NODES + n) * FDIM + c];
        g_z[(size_t)n * FDIM + c] = acc;
    }
}

// -------- final 128->2 head --------------------------------------------------
__global__ void __launch_bounds__(128)
cls_final_kernel(const float* __restrict__ W2, const float* __restrict__ b2,
                 float* __restrict__ out) {
    int n = blockIdx.x;
    int t = threadIdx.x;  // 128
    float h = g_hcls[(size_t)n * 128 + t];
    float a0 = h * W2[t * 2 + 0];
    float a1 = h * W2[t * 2 + 1];
    __shared__ float r0[4], r1[4];
#pragma unroll
    for (int o = 16; o; o >>= 1) {
        a0 += __shfl_down_sync(0xffffffffu, a0, o);
        a1 += __shfl_down_sync(0xffffffffu, a1, o);
    }
    if ((t & 31) == 0) { r0[t >> 5] = a0; r1[t >> 5] = a1; }
    __syncthreads();
    if (t == 0) {
        out[n * 2 + 0] = r0[0] + r0[1] + r0[2] + r0[3] + b2[0];
        out[n * 2 + 1] = r1[0] + r1[1] + r1[2] + r1[3] + b2[1];
    }
}

// ---------------- host -------------------------------------------------------
extern "C" void kernel_launch(void* const* d_in, const int* in_sizes, int n_in,
                              void* d_out, int out_size) {
    const float* x       = (const float*)d_in[0];
    const int*   edges   = (const int*)d_in[1];
    const float* proj_W  = (const float*)d_in[2];
    const float* proj_b  = (const float*)d_in[3];
    const float* gat_W   = (const float*)d_in[4];
    const float* gat_asrc= (const float*)d_in[5];
    const float* gat_adst= (const float*)d_in[6];
    const float* gat_b   = (const float*)d_in[7];
    const float* sem_W1  = (const float*)d_in[8];
    const float* sem_b1  = (const float*)d_in[9];
    const float* sem_W2  = (const float*)d_in[10];
    const float* cls_W1  = (const float*)d_in[11];
    const float* cls_b1  = (const float*)d_in[12];
    const float* cls_W2  = (const float*)d_in[13];
    const float* cls_b2  = (const float*)d_in[14];
    float* out = (float*)d_out;

    float *p_h0, *p_h, *p_hp, *p_embs, *p_hsem, *p_z, *p_hcls;
    cudaGetSymbolAddress((void**)&p_h0,   g_h0);
    cudaGetSymbolAddress((void**)&p_h,    g_h);
    cudaGetSymbolAddress((void**)&p_hp,   g_hp);
    cudaGetSymbolAddress((void**)&p_embs, g_embs);
    cudaGetSymbolAddress((void**)&p_hsem, g_hsem);
    cudaGetSymbolAddress((void**)&p_z,    g_z);
    cudaGetSymbolAddress((void**)&p_hcls, g_hcls);

    const int M = N_NODES;
    dim3 gproj((M + 63) / 64, 256 / 64);
    gemm_kernel<1><<<gproj, 256>>>(x, proj_W, proj_b, p_h0, M, 128, 256);

    const int scoreGrid = (N_NODES * NHEAD + 255) / 256;
    const int edgeGridAB = (ET * NHEAD + 255) / 256;
    const int edgeGridC  = (ET + 3) / 4;
    const int initGrid = (N_NODES * FDIM + 255) / 256;

    for (int p = 0; p < 3; p++) {
        const int* srcs = edges + (size_t)p * 2 * EDGES;
        const int* dsts = srcs + EDGES;
        for (int l = 0; l < 2; l++) {
            const float* W  = gat_W    + (size_t)(p * 2 + l) * 256 * 256;
            const float* as = gat_asrc + (size_t)(p * 2 + l) * NHEAD * DH;
            const float* ad = gat_adst + (size_t)(p * 2 + l) * NHEAD * DH;
            const float* gb = gat_b    + (size_t)(p * 2 + l) * 256;
            const float* hin = (l == 0) ? p_h0 : p_h;
            float* hout = (l == 0) ? p_h : (p_embs + (size_t)p * N_NODES * FDIM);

            gemm_kernel<0><<<gproj, 256>>>(hin, W, nullptr, p_hp, M, 256, 256);
            scores_kernel<<<scoreGrid, 256>>>(p_hp, as, ad);
            init_kernel<<<initGrid, 256>>>();
            passA_kernel<<<edgeGridAB, 256>>>(srcs, dsts);
            passB_kernel<<<edgeGridAB, 256>>>(srcs, dsts);
            passC_kernel<<<edgeGridC, 256>>>(srcs, dsts);
            epilogue_kernel<<<initGrid, 256>>>(gb, hout);
        }
    }

    // semantic attention
    dim3 gsem((3 * N_NODES + 63) / 64, 128 / 64);
    gemm_kernel<1><<<gsem, 256>>>(p_embs, sem_W1, sem_b1, p_hsem, 3 * N_NODES, 256, 128);
    semfuse_kernel<<<N_NODES, 128>>>(sem_W2);

    // classifier
    dim3 gcls((M + 63) / 64, 128 / 64);
    gemm_kernel<2><<<gcls, 256>>>(p_z, cls_W1, cls_b1, p_hcls, M, 256, 128);
    cls_final_kernel<<<N_NODES, 128>>>(cls_W2, cls_b2, out);
}

// round 4
// speedup vs baseline: 1.7363x; 1.7363x over previous
#include <cuda_runtime.h>
#include <cuda_bf16.h>
#include <math.h>

#define N_NODES 50000
#define EDGES   800000
#define ET      (EDGES + N_NODES)   // edges + self loops = 850000
#define NHEAD   8
#define DH      32
#define FDIM    256

// ---------------- scratch (device globals; no allocation allowed) ------------
__device__ float g_h0[N_NODES * FDIM];
__device__ float g_h[N_NODES * FDIM];
__device__ float g_hp[N_NODES * FDIM];
__device__ float g_embs[3 * N_NODES * FDIM];
__device__ float g_ssrc[N_NODES * NHEAD];
__device__ float g_sdst[N_NODES * NHEAD];
__device__ float g_hsem[3 * N_NODES * 128];
__device__ float g_z[N_NODES * FDIM];
__device__ float g_hcls[N_NODES * 128];

// CSR (built once per launch; edges constant)
__device__ int g_deg[3 * N_NODES];
__device__ int g_fill[3 * N_NODES];
__device__ int g_ptr[3 * (N_NODES + 1)];
__device__ int g_csr[3 * ET];

// ================= CSR build =================================================
__global__ void csr_zero_kernel() {
    int idx = blockIdx.x * blockDim.x + threadIdx.x;
    if (idx < 3 * N_NODES) g_deg[idx] = 0;
}

__global__ void csr_hist_kernel(const int* __restrict__ edges) {
    int idx = blockIdx.x * blockDim.x + threadIdx.x;
    int p = blockIdx.y;
    if (idx >= ET) return;
    int d = (idx < EDGES) ? edges[(size_t)p * 2 * EDGES + EDGES + idx] : idx - EDGES;
    atomicAdd(&g_deg[p * N_NODES + d], 1);
}

// one block per metapath; 1024 threads; chunked warp-scan
__global__ void __launch_bounds__(1024) csr_scan_kernel() {
    int p = blockIdx.x;
    int tid = threadIdx.x;
    int lane = tid & 31, wid = tid >> 5;
    __shared__ int swarp[32];
    __shared__ int s_carry;
    if (tid == 0) s_carry = 0;
    __syncthreads();
    for (int base = 0; base < N_NODES; base += 1024) {
        int i = base + tid;
        int v = (i < N_NODES) ? g_deg[p * N_NODES + i] : 0;
        int incl = v;
#pragma unroll
        for (int off = 1; off < 32; off <<= 1) {
            int t = __shfl_up_sync(0xffffffffu, incl, off);
            if (lane >= off) incl += t;
        }
        if (lane == 31) swarp[wid] = incl;
        __syncthreads();
        if (wid == 0) {
            int s = swarp[lane];
#pragma unroll
            for (int off = 1; off < 32; off <<= 1) {
                int t = __shfl_up_sync(0xffffffffu, s, off);
                if (lane >= off) s += t;
            }
            swarp[lane] = s;
        }
        __syncthreads();
        int woff = (wid > 0) ? swarp[wid - 1] : 0;
        incl += woff;
        int excl = incl - v;
        int carry = s_carry;
        if (i < N_NODES) {
            g_ptr[p * (N_NODES + 1) + i] = carry + excl;
            g_fill[p * N_NODES + i] = carry + excl;
        }
        int total = swarp[31];
        __syncthreads();
        if (tid == 0) s_carry = carry + total;
        __syncthreads();
    }
    if (tid == 0) g_ptr[p * (N_NODES + 1) + N_NODES] = s_carry;
}

__global__ void csr_scatter_kernel(const int* __restrict__ edges) {
    int idx = blockIdx.x * blockDim.x + threadIdx.x;
    int p = blockIdx.y;
    if (idx >= ET) return;
    int s, d;
    if (idx < EDGES) {
        s = edges[(size_t)p * 2 * EDGES + idx];
        d = edges[(size_t)p * 2 * EDGES + EDGES + idx];
    } else {
        s = idx - EDGES; d = s;
    }
    int pos = atomicAdd(&g_fill[p * N_NODES + d], 1);
    g_csr[(size_t)p * ET + pos] = s;
}

// ================= GEMM: 128x128 tile, BK=8, 256 thr, 8x8 micro, dbl-buffered
// EPI: 0 = none, 1 = +bias, 2 = +bias+relu
template <int EPI>
__global__ void __launch_bounds__(256)
gemm128(const float* __restrict__ A, const float* __restrict__ B,
        const float* __restrict__ bias, float* __restrict__ C,
        int M, int K, int Nc) {
    __shared__ float As[2][8][128];
    __shared__ float Bs[2][8][128];
    const int bm = blockIdx.x * 128;
    const int bn = blockIdx.y * 128;
    const int tid = threadIdx.x;
    const int tx = tid & 15, ty = tid >> 4;

    const int arow = tid >> 1;          // 0..127
    const int acol = (tid & 1) * 4;     // 0 / 4
    const int brow = tid >> 5;          // 0..7
    const int bcol = (tid & 31) * 4;    // 0..124

    const bool avalid = (bm + arow) < M;
    const float* Aptr = A + (size_t)(bm + arow) * K + acol;
    const float* Bptr = B + (size_t)brow * Nc + bn + bcol;

    float4 ra = avalid ? *(const float4*)Aptr : make_float4(0.f, 0.f, 0.f, 0.f);
    float4 rb = *(const float4*)Bptr;
    As[0][acol + 0][arow] = ra.x; As[0][acol + 1][arow] = ra.y;
    As[0][acol + 2][arow] = ra.z; As[0][acol + 3][arow] = ra.w;
    *(float4*)&Bs[0][brow][bcol] = rb;
    __syncthreads();

    float acc[8][8];
#pragma unroll
    for (int i = 0; i < 8; i++)
#pragma unroll
        for (int j = 0; j < 8; j++) acc[i][j] = 0.f;

    int cur = 0;
    for (int k0 = 8; k0 < K; k0 += 8) {
        ra = avalid ? *(const float4*)(Aptr + k0) : make_float4(0.f, 0.f, 0.f, 0.f);
        rb = *(const float4*)(Bptr + (size_t)k0 * Nc);
#pragma unroll
        for (int k = 0; k < 8; k++) {
            float a[8], b[8];
            *(float4*)(a)     = *(const float4*)&As[cur][k][ty * 8];
            *(float4*)(a + 4) = *(const float4*)&As[cur][k][ty * 8 + 4];
            *(float4*)(b)     = *(const float4*)&Bs[cur][k][tx * 8];
            *(float4*)(b + 4) = *(const float4*)&Bs[cur][k][tx * 8 + 4];
#pragma unroll
            for (int i = 0; i < 8; i++)
#pragma unroll
                for (int j = 0; j < 8; j++) acc[i][j] = fmaf(a[i], b[j], acc[i][j]);
        }
        int nxt = cur ^ 1;
        As[nxt][acol + 0][arow] = ra.x; As[nxt][acol + 1][arow] = ra.y;
        As[nxt][acol + 2][arow] = ra.z; As[nxt][acol + 3][arow] = ra.w;
        *(float4*)&Bs[nxt][brow][bcol] = rb;
        __syncthreads();
        cur = nxt;
    }
#pragma unroll
    for (int k = 0; k < 8; k++) {
        float a[8], b[8];
        *(float4*)(a)     = *(const float4*)&As[cur][k][ty * 8];
        *(float4*)(a + 4) = *(const float4*)&As[cur][k][ty * 8 + 4];
        *(float4*)(b)     = *(const float4*)&Bs[cur][k][tx * 8];
        *(float4*)(b + 4) = *(const float4*)&Bs[cur][k][tx * 8 + 4];
#pragma unroll
        for (int i = 0; i < 8; i++)
#pragma unroll
            for (int j = 0; j < 8; j++) acc[i][j] = fmaf(a[i], b[j], acc[i][j]);
    }

#pragma unroll
    for (int i = 0; i < 8; i++) {
        int m = bm + ty * 8 + i;
        if (m >= M) continue;
#pragma unroll
        for (int j4 = 0; j4 < 8; j4 += 4) {
            int n = bn + tx * 8 + j4;
            float4 v = make_float4(acc[i][j4], acc[i][j4 + 1], acc[i][j4 + 2], acc[i][j4 + 3]);
            if (EPI >= 1) {
                const float4 bv = *(const float4*)(bias + n);
                v.x += bv.x; v.y += bv.y; v.z += bv.z; v.w += bv.w;
            }
            if (EPI == 2) {
                v.x = fmaxf(v.x, 0.f); v.y = fmaxf(v.y, 0.f);
                v.z = fmaxf(v.z, 0.f); v.w = fmaxf(v.w, 0.f);
            }
            *(float4*)(C + (size_t)m * Nc + n) = v;
        }
    }
}

// -------- per-(node,head) attention logits -----------------------------------
__global__ void scores_kernel(const float* __restrict__ hp,
                              const float* __restrict__ asrc,
                              const float* __restrict__ adst) {
    int idx = blockIdx.x * blockDim.x + threadIdx.x;
    if (idx >= N_NODES * NHEAD) return;
    int n = idx >> 3, h = idx & 7;
    const float4* v = (const float4*)(hp + (size_t)n * FDIM + h * DH);
    const float4* a = (const float4*)(asrc + h * DH);
    const float4* b = (const float4*)(adst + h * DH);
    float s1 = 0.f, s2 = 0.f;
#pragma unroll
    for (int i = 0; i < 8; i++) {
        float4 x = v[i], p = a[i], q = b[i];
        s1 += x.x * p.x + x.y * p.y + x.z * p.z + x.w * p.w;
        s2 += x.x * q.x + x.y * q.y + x.z * q.z + x.w * q.w;
    }
    g_ssrc[idx] = s1;
    g_sdst[idx] = s2;
}

// ======== fused per-node aggregation: max -> denom -> weighted sum + bias+ELU
// one 64-thread block per dst node; no atomics.
__global__ void __launch_bounds__(64)
agg_kernel(const int* __restrict__ ptr, const int* __restrict__ csrc,
           const float* __restrict__ hp, const float* __restrict__ bias,
           float* __restrict__ out) {
    const int n = blockIdx.x;
    const int t = threadIdx.x;
    const int lane = t & 31, w = t >> 5;
    const int p0 = ptr[n];
    const int deg = ptr[n + 1] - p0;

    __shared__ float sm[2][8];
    __shared__ float sMax[8];
    __shared__ float sInv[8];
    __shared__ int se[64];

    // dst scores (broadcast load)
    float dh[8];
    {
        float4 d0 = ((const float4*)(g_sdst + (size_t)n * 8))[0];
        float4 d1 = ((const float4*)(g_sdst + (size_t)n * 8))[1];
        dh[0] = d0.x; dh[1] = d0.y; dh[2] = d0.z; dh[3] = d0.w;
        dh[4] = d1.x; dh[5] = d1.y; dh[6] = d1.z; dh[7] = d1.w;
    }

    // ---- phase A1: per-head max ----
    float mh[8];
#pragma unroll
    for (int h = 0; h < 8; h++) mh[h] = -1e30f;
    for (int i = t; i < deg; i += 64) {
        int s = csrc[p0 + i];
        float4 s0 = ((const float4*)(g_ssrc + (size_t)s * 8))[0];
        float4 s1 = ((const float4*)(g_ssrc + (size_t)s * 8))[1];
        float e[8];
        e[0] = s0.x + dh[0]; e[1] = s0.y + dh[1]; e[2] = s0.z + dh[2]; e[3] = s0.w + dh[3];
        e[4] = s1.x + dh[4]; e[5] = s1.y + dh[5]; e[6] = s1.z + dh[6]; e[7] = s1.w + dh[7];
#pragma unroll
        for (int h = 0; h < 8; h++) {
            float v = e[h] > 0.f ? e[h] : 0.2f * e[h];
            mh[h] = fmaxf(mh[h], v);
        }
    }
#pragma unroll
    for (int off = 16; off; off >>= 1)
#pragma unroll
        for (int h = 0; h < 8; h++)
            mh[h] = fmaxf(mh[h], __shfl_xor_sync(0xffffffffu, mh[h], off));
    if (lane == 0)
#pragma unroll
        for (int h = 0; h < 8; h++) sm[w][h] = mh[h];
    __syncthreads();
    float M[8];
#pragma unroll
    for (int h = 0; h < 8; h++) M[h] = fmaxf(sm[0][h], sm[1][h]);
    __syncthreads();

    // ---- phase A2: per-head denom ----
    float sumh[8];
#pragma unroll
    for (int h = 0; h < 8; h++) sumh[h] = 0.f;
    for (int i = t; i < deg; i += 64) {
        int s = csrc[p0 + i];
        float4 s0 = ((const float4*)(g_ssrc + (size_t)s * 8))[0];
        float4 s1 = ((const float4*)(g_ssrc + (size_t)s * 8))[1];
        float e[8];
        e[0] = s0.x + dh[0]; e[1] = s0.y + dh[1]; e[2] = s0.z + dh[2]; e[3] = s0.w + dh[3];
        e[4] = s1.x + dh[4]; e[5] = s1.y + dh[5]; e[6] = s1.z + dh[6]; e[7] = s1.w + dh[7];
#pragma unroll
        for (int h = 0; h < 8; h++) {
            float v = e[h] > 0.f ? e[h] : 0.2f * e[h];
            sumh[h] += expf(v - M[h]);
        }
    }
#pragma unroll
    for (int off = 16; off; off >>= 1)
#pragma unroll
        for (int h = 0; h < 8; h++)
            sumh[h] += __shfl_xor_sync(0xffffffffu, sumh[h], off);
    if (lane == 0)
#pragma unroll
        for (int h = 0; h < 8; h++) sm[w][h] = sumh[h];
    __syncthreads();
    if (t < 8) {
        sMax[t] = M[t];
        sInv[t] = 1.f / (sm[0][t] + sm[1][t]);
    }
    __syncthreads();

    // ---- phase B: weighted accumulation ----
    const int myh = t >> 3;
    const float mym = sMax[myh];
    const float myinv = sInv[myh];
    const float mysd = dh[myh];
    float4 acc = make_float4(0.f, 0.f, 0.f, 0.f);

    for (int c0 = 0; c0 < deg; c0 += 64) {
        int cnt = min(64, deg - c0);
        __syncthreads();
        if (t < cnt) se[t] = csrc[p0 + c0 + t];
        __syncthreads();
        for (int i = 0; i < cnt; i++) {
            int s = se[i];
            float alpha = 0.f;
            if ((lane & 7) == 0) {
                float e = g_ssrc[(size_t)s * 8 + myh] + mysd;
                e = e > 0.f ? e : 0.2f * e;
                alpha = expf(e - mym) * myinv;
            }
            alpha = __shfl_sync(0xffffffffu, alpha, lane & 24);
            float4 x = ((const float4*)(hp + (size_t)s * FDIM))[t];
            acc.x = fmaf(alpha, x.x, acc.x);
            acc.y = fmaf(alpha, x.y, acc.y);
            acc.z = fmaf(alpha, x.z, acc.z);
            acc.w = fmaf(alpha, x.w, acc.w);
        }
    }

    // bias + ELU, direct store
    float4 bv = ((const float4*)bias)[t];
    float v;
    v = acc.x + bv.x; acc.x = v > 0.f ? v : expm1f(v);
    v = acc.y + bv.y; acc.y = v > 0.f ? v : expm1f(v);
    v = acc.z + bv.z; acc.z = v > 0.f ? v : expm1f(v);
    v = acc.w + bv.w; acc.w = v > 0.f ? v : expm1f(v);
    ((float4*)(out + (size_t)n * FDIM))[t] = acc;
}

// -------- semantic attention fuse: scores -> softmax -> weighted sum ---------
__global__ void __launch_bounds__(128)
semfuse_kernel(const float* __restrict__ semW2) {
    int n = blockIdx.x;
    int t = threadIdx.x;  // 128
    __shared__ float red[4];
    __shared__ float w[3];
    float sloc[3];
    for (int p = 0; p < 3; p++) {
        float v = tanhf(g_hsem[((size_t)p * N_NODES + n) * 128 + t]) * semW2[t];
#pragma unroll
        for (int o = 16; o; o >>= 1) v += __shfl_down_sync(0xffffffffu, v, o);
        if ((t & 31) == 0) red[t >> 5] = v;
        __syncthreads();
        if (t == 0) sloc[p] = red[0] + red[1] + red[2] + red[3];
        __syncthreads();
    }
    if (t == 0) {
        float mx = fmaxf(sloc[0], fmaxf(sloc[1], sloc[2]));
        float e0 = expf(sloc[0] - mx), e1 = expf(sloc[1] - mx), e2 = expf(sloc[2] - mx);
        float inv = 1.f / (e0 + e1 + e2);
        w[0] = e0 * inv; w[1] = e1 * inv; w[2] = e2 * inv;
    }
    __syncthreads();
    for (int c = t; c < FDIM; c += 128) {
        float acc = 0.f;
#pragma unroll
        for (int p = 0; p < 3; p++)
            acc += w[p] * g_embs[((size_t)p * N_NODES + n) * FDIM + c];
        g_z[(size_t)n * FDIM + c] = acc;
    }
}

// -------- final 128->2 head --------------------------------------------------
__global__ void __launch_bounds__(128)
cls_final_kernel(const float* __restrict__ W2, const float* __restrict__ b2,
                 float* __restrict__ out) {
    int n = blockIdx.x;
    int t = threadIdx.x;  // 128
    float h = g_hcls[(size_t)n * 128 + t];
    float a0 = h * W2[t * 2 + 0];
    float a1 = h * W2[t * 2 + 1];
    __shared__ float r0[4], r1[4];
#pragma unroll
    for (int o = 16; o; o >>= 1) {
        a0 += __shfl_down_sync(0xffffffffu, a0, o);
        a1 += __shfl_down_sync(0xffffffffu, a1, o);
    }
    if ((t & 31) == 0) { r0[t >> 5] = a0; r1[t >> 5] = a1; }
    __syncthreads();
    if (t == 0) {
        out[n * 2 + 0] = r0[0] + r0[1] + r0[2] + r0[3] + b2[0];
        out[n * 2 + 1] = r1[0] + r1[1] + r1[2] + r1[3] + b2[1];
    }
}

// ---------------- host -------------------------------------------------------
extern "C" void kernel_launch(void* const* d_in, const int* in_sizes, int n_in,
                              void* d_out, int out_size) {
    const float* x       = (const float*)d_in[0];
    const int*   edges   = (const int*)d_in[1];
    const float* proj_W  = (const float*)d_in[2];
    const float* proj_b  = (const float*)d_in[3];
    const float* gat_W   = (const float*)d_in[4];
    const float* gat_asrc= (const float*)d_in[5];
    const float* gat_adst= (const float*)d_in[6];
    const float* gat_b   = (const float*)d_in[7];
    const float* sem_W1  = (const float*)d_in[8];
    const float* sem_b1  = (const float*)d_in[9];
    const float* sem_W2  = (const float*)d_in[10];
    const float* cls_W1  = (const float*)d_in[11];
    const float* cls_b1  = (const float*)d_in[12];
    const float* cls_W2  = (const float*)d_in[13];
    const float* cls_b2  = (const float*)d_in[14];
    float* out = (float*)d_out;

    float *p_h0, *p_h, *p_hp, *p_embs, *p_hsem, *p_z, *p_hcls;
    int *p_ptr, *p_csr;
    cudaGetSymbolAddress((void**)&p_h0,   g_h0);
    cudaGetSymbolAddress((void**)&p_h,    g_h);
    cudaGetSymbolAddress((void**)&p_hp,   g_hp);
    cudaGetSymbolAddress((void**)&p_embs, g_embs);
    cudaGetSymbolAddress((void**)&p_hsem, g_hsem);
    cudaGetSymbolAddress((void**)&p_z,    g_z);
    cudaGetSymbolAddress((void**)&p_hcls, g_hcls);
    cudaGetSymbolAddress((void**)&p_ptr,  g_ptr);
    cudaGetSymbolAddress((void**)&p_csr,  g_csr);

    // ---- CSR build (edges are constant across the forward) ----
    csr_zero_kernel<<<(3 * N_NODES + 255) / 256, 256>>>();
    dim3 ge((ET + 255) / 256, 3);
    csr_hist_kernel<<<ge, 256>>>(edges);
    csr_scan_kernel<<<3, 1024>>>();
    csr_scatter_kernel<<<ge, 256>>>(edges);

    const int M = N_NODES;
    dim3 gproj((M + 127) / 128, 2);
    gemm128<1><<<gproj, 256>>>(x, proj_W, proj_b, p_h0, M, 128, 256);

    const int scoreGrid = (N_NODES * NHEAD + 255) / 256;

    for (int p = 0; p < 3; p++) {
        const int* ptr = p_ptr + (size_t)p * (N_NODES + 1);
        const int* csr = p_csr + (size_t)p * ET;
        for (int l = 0; l < 2; l++) {
            const float* W  = gat_W    + (size_t)(p * 2 + l) * 256 * 256;
            const float* as = gat_asrc + (size_t)(p * 2 + l) * NHEAD * DH;
            const float* ad = gat_adst + (size_t)(p * 2 + l) * NHEAD * DH;
            const float* gb = gat_b    + (size_t)(p * 2 + l) * 256;
            const float* hin = (l == 0) ? p_h0 : p_h;
            float* hout = (l == 0) ? p_h : (p_embs + (size_t)p * N_NODES * FDIM);

            gemm128<0><<<gproj, 256>>>(hin, W, nullptr, p_hp, M, 256, 256);
            scores_kernel<<<scoreGrid, 256>>>(p_hp, as, ad);
            agg_kernel<<<N_NODES, 64>>>(ptr, csr, p_hp, gb, hout);
        }
    }

    // semantic attention
    dim3 gsem((3 * N_NODES + 127) / 128, 1);
    gemm128<1><<<gsem, 256>>>(p_embs, sem_W1, sem_b1, p_hsem, 3 * N_NODES, 256, 128);
    semfuse_kernel<<<N_NODES, 128>>>(sem_W2);

    // classifier
    dim3 gcls((M + 127) / 128, 1);
    gemm128<2><<<gcls, 256>>>(p_z, cls_W1, cls_b1, p_hcls, M, 256, 128);
    cls_final_kernel<<<N_NODES, 128>>>(cls_W2, cls_b2, out);
}

// round 6
// speedup vs baseline: 2.6492x; 1.5258x over previous
#include <cuda_runtime.h>
#include <cuda_bf16.h>
#include <math.h>
#include <stdint.h>

#define N_NODES 50000
#define EDGES   800000
#define ET      (EDGES + N_NODES)   // edges + self loops = 850000
#define NHEAD   8
#define DH      32
#define FDIM    256

// ---------------- scratch (device globals; no allocation allowed) ------------
__device__ float g_h0[N_NODES * FDIM];
__device__ float g_h[N_NODES * FDIM];
__device__ float g_hp[N_NODES * FDIM];
__device__ float g_embs[3 * N_NODES * FDIM];
__device__ float g_ssrc[N_NODES * NHEAD];
__device__ float g_sdst[N_NODES * NHEAD];
__device__ float g_hsem[3 * N_NODES * 128];
__device__ float g_z[N_NODES * FDIM];
__device__ float g_hcls[N_NODES * 128];

// CSR (built once per launch; edges constant)
__device__ int g_deg[3 * N_NODES];
__device__ int g_fill[3 * N_NODES];
__device__ int g_ptr[3 * (N_NODES + 1)];
__device__ int g_csr[3 * ET];

// ================= CSR build =================================================
__global__ void csr_zero_kernel() {
    int idx = blockIdx.x * blockDim.x + threadIdx.x;
    if (idx < 3 * N_NODES) g_deg[idx] = 0;
}

__global__ void csr_hist_kernel(const int* __restrict__ edges) {
    int idx = blockIdx.x * blockDim.x + threadIdx.x;
    int p = blockIdx.y;
    if (idx >= ET) return;
    int d = (idx < EDGES) ? edges[(size_t)p * 2 * EDGES + EDGES + idx] : idx - EDGES;
    atomicAdd(&g_deg[p * N_NODES + d], 1);
}

// one block per metapath; 1024 threads; chunked warp-scan
__global__ void __launch_bounds__(1024) csr_scan_kernel() {
    int p = blockIdx.x;
    int tid = threadIdx.x;
    int lane = tid & 31, wid = tid >> 5;
    __shared__ int swarp[32];
    __shared__ int s_carry;
    if (tid == 0) s_carry = 0;
    __syncthreads();
    for (int base = 0; base < N_NODES; base += 1024) {
        int i = base + tid;
        int v = (i < N_NODES) ? g_deg[p * N_NODES + i] : 0;
        int incl = v;
#pragma unroll
        for (int off = 1; off < 32; off <<= 1) {
            int t = __shfl_up_sync(0xffffffffu, incl, off);
            if (lane >= off) incl += t;
        }
        if (lane == 31) swarp[wid] = incl;
        __syncthreads();
        if (wid == 0) {
            int s = swarp[lane];
#pragma unroll
            for (int off = 1; off < 32; off <<= 1) {
                int t = __shfl_up_sync(0xffffffffu, s, off);
                if (lane >= off) s += t;
            }
            swarp[lane] = s;
        }
        __syncthreads();
        int woff = (wid > 0) ? swarp[wid - 1] : 0;
        incl += woff;
        int excl = incl - v;
        int carry = s_carry;
        if (i < N_NODES) {
            g_ptr[p * (N_NODES + 1) + i] = carry + excl;
            g_fill[p * N_NODES + i] = carry + excl;
        }
        int total = swarp[31];
        __syncthreads();
        if (tid == 0) s_carry = carry + total;
        __syncthreads();
    }
    if (tid == 0) g_ptr[p * (N_NODES + 1) + N_NODES] = s_carry;
}

__global__ void csr_scatter_kernel(const int* __restrict__ edges) {
    int idx = blockIdx.x * blockDim.x + threadIdx.x;
    int p = blockIdx.y;
    if (idx >= ET) return;
    int s, d;
    if (idx < EDGES) {
        s = edges[(size_t)p * 2 * EDGES + idx];
        d = edges[(size_t)p * 2 * EDGES + EDGES + idx];
    } else {
        s = idx - EDGES; d = s;
    }
    int pos = atomicAdd(&g_fill[p * N_NODES + d], 1);
    g_csr[(size_t)p * ET + pos] = s;
}

// ================= tf32 tensor-core GEMM =====================================
// C[M,Nc] = A[M,K] @ B[K,Nc] (+bias)(+relu), fp32 accum, tf32 (RNA) inputs.
// 128x128 block tile, BK=32, 256 threads (2x4 warps), 64x32 warp tile,
// mma.sync.aligned.m16n8k8.row.col.f32.tf32.tf32.f32

__device__ __forceinline__ uint32_t f2tf32(float f) {
    uint32_t r;
    asm("cvt.rna.tf32.f32 %0, %1;" : "=r"(r) : "f"(f));
    return r;
}

__device__ __forceinline__ void mma_tf32(float* cc,
                                         uint32_t a0, uint32_t a1, uint32_t a2, uint32_t a3,
                                         uint32_t b0, uint32_t b1) {
    asm volatile(
        "mma.sync.aligned.m16n8k8.row.col.f32.tf32.tf32.f32 "
        "{%0,%1,%2,%3}, {%4,%5,%6,%7}, {%8,%9}, {%0,%1,%2,%3};"
        : "+f"(cc[0]), "+f"(cc[1]), "+f"(cc[2]), "+f"(cc[3])
        : "r"(a0), "r"(a1), "r"(a2), "r"(a3), "r"(b0), "r"(b1));
}

template <int EPI>  // 0 none, 1 +bias, 2 +bias+relu
__global__ void __launch_bounds__(256)
gemm_tf32(const float* __restrict__ A, const float* __restrict__ B,
          const float* __restrict__ bias, float* __restrict__ C,
          int M, int K, int Nc) {
    __shared__ uint32_t As[128][36];   // [m][k], pad 4 -> conflict-free frag loads
    __shared__ uint32_t Bs[32][132];   // [k][n], pad 4

    const int bm = blockIdx.x * 128;
    const int bn = blockIdx.y * 128;
    const int tid = threadIdx.x;
    const int lane = tid & 31;
    const int warp = tid >> 5;
    const int wm = (warp & 1) * 64;     // warp M offset
    const int wn = (warp >> 1) * 32;    // warp N offset
    const int gq = lane >> 2;           // group id (0..7)
    const int cq = lane & 3;            // thread-in-group (0..3)

    // gmem tile-load coordinates (each thread: 4 float4 of A, 4 float4 of B)
    const int ar = tid >> 3;            // + 32*i
    const int ac = (tid & 7) * 4;
    const int br = tid >> 5;            // + 8*i
    const int bc = (tid & 31) * 4;

    float4 ra[4], rb[4];
#pragma unroll
    for (int i = 0; i < 4; i++) {
        int row = ar + 32 * i;
        ra[i] = (bm + row < M) ? *(const float4*)(A + (size_t)(bm + row) * K + ac)
                               : make_float4(0.f, 0.f, 0.f, 0.f);
        rb[i] = *(const float4*)(B + (size_t)(br + 8 * i) * Nc + bn + bc);
    }
#pragma unroll
    for (int i = 0; i < 4; i++) {
        int row = ar + 32 * i;
        As[row][ac + 0] = f2tf32(ra[i].x); As[row][ac + 1] = f2tf32(ra[i].y);
        As[row][ac + 2] = f2tf32(ra[i].z); As[row][ac + 3] = f2tf32(ra[i].w);
        int kr = br + 8 * i;
        Bs[kr][bc + 0] = f2tf32(rb[i].x); Bs[kr][bc + 1] = f2tf32(rb[i].y);
        Bs[kr][bc + 2] = f2tf32(rb[i].z); Bs[kr][bc + 3] = f2tf32(rb[i].w);
    }
    __syncthreads();

    float acc[4][4][4];
#pragma unroll
    for (int i = 0; i < 4; i++)
#pragma unroll
        for (int j = 0; j < 4; j++)
#pragma unroll
            for (int q = 0; q < 4; q++) acc[i][j][q] = 0.f;

#define COMPUTE_TILE()                                                          \
    {                                                                           \
        _Pragma("unroll")                                                       \
        for (int ks = 0; ks < 4; ks++) {                                        \
            const int kb = ks * 8;                                              \
            uint32_t af[4][4], bf[4][2];                                        \
            _Pragma("unroll")                                                   \
            for (int i = 0; i < 4; i++) {                                       \
                int r0 = wm + i * 16 + gq;                                      \
                af[i][0] = As[r0][kb + cq];                                     \
                af[i][1] = As[r0 + 8][kb + cq];                                 \
                af[i][2] = As[r0][kb + cq + 4];                                 \
                af[i][3] = As[r0 + 8][kb + cq + 4];                             \
            }                                                                   \
            _Pragma("unroll")                                                   \
            for (int j = 0; j < 4; j++) {                                       \
                int col = wn + j * 8 + gq;                                      \
                bf[j][0] = Bs[kb + cq][col];                                    \
                bf[j][1] = Bs[kb + cq + 4][col];                                \
            }                                                                   \
            _Pragma("unroll")                                                   \
            for (int i = 0; i < 4; i++)                                         \
                _Pragma("unroll")                                               \
                for (int j = 0; j < 4; j++)                                     \
                    mma_tf32(acc[i][j], af[i][0], af[i][1], af[i][2], af[i][3], \
                             bf[j][0], bf[j][1]);                               \
        }                                                                       \
    }

    for (int k0 = 32; k0 < K; k0 += 32) {
#pragma unroll
        for (int i = 0; i < 4; i++) {
            int row = ar + 32 * i;
            ra[i] = (bm + row < M) ? *(const float4*)(A + (size_t)(bm + row) * K + k0 + ac)
                                   : make_float4(0.f, 0.f, 0.f, 0.f);
            rb[i] = *(const float4*)(B + (size_t)(k0 + br + 8 * i) * Nc + bn + bc);
        }
        COMPUTE_TILE();
        __syncthreads();
#pragma unroll
        for (int i = 0; i < 4; i++) {
            int row = ar + 32 * i;
            As[row][ac + 0] = f2tf32(ra[i].x); As[row][ac + 1] = f2tf32(ra[i].y);
            As[row][ac + 2] = f2tf32(ra[i].z); As[row][ac + 3] = f2tf32(ra[i].w);
            int kr = br + 8 * i;
            Bs[kr][bc + 0] = f2tf32(rb[i].x); Bs[kr][bc + 1] = f2tf32(rb[i].y);
            Bs[kr][bc + 2] = f2tf32(rb[i].z); Bs[kr][bc + 3] = f2tf32(rb[i].w);
        }
        __syncthreads();
    }
    COMPUTE_TILE();
#undef COMPUTE_TILE

    // epilogue: float2 stores (c0,c1 at row r0; c2,c3 at row r0+8, same cols)
#pragma unroll
    for (int i = 0; i < 4; i++) {
        int r0 = bm + wm + i * 16 + gq;
        int r1 = r0 + 8;
#pragma unroll
        for (int j = 0; j < 4; j++) {
            int col = bn + wn + j * 8 + 2 * cq;
            float2 v0 = make_float2(acc[i][j][0], acc[i][j][1]);
            float2 v1 = make_float2(acc[i][j][2], acc[i][j][3]);
            if (EPI >= 1) {
                float2 bv = *(const float2*)(bias + col);
                v0.x += bv.x; v0.y += bv.y; v1.x += bv.x; v1.y += bv.y;
            }
            if (EPI == 2) {
                v0.x = fmaxf(v0.x, 0.f); v0.y = fmaxf(v0.y, 0.f);
                v1.x = fmaxf(v1.x, 0.f); v1.y = fmaxf(v1.y, 0.f);
            }
            if (r0 < M) *(float2*)(C + (size_t)r0 * Nc + col) = v0;
            if (r1 < M) *(float2*)(C + (size_t)r1 * Nc + col) = v1;
        }
    }
}

// -------- per-(node,head) attention logits -----------------------------------
__global__ void scores_kernel(const float* __restrict__ hp,
                              const float* __restrict__ asrc,
                              const float* __restrict__ adst) {
    int idx = blockIdx.x * blockDim.x + threadIdx.x;
    if (idx >= N_NODES * NHEAD) return;
    int n = idx >> 3, h = idx & 7;
    const float4* v = (const float4*)(hp + (size_t)n * FDIM + h * DH);
    const float4* a = (const float4*)(asrc + h * DH);
    const float4* b = (const float4*)(adst + h * DH);
    float s1 = 0.f, s2 = 0.f;
#pragma unroll
    for (int i = 0; i < 8; i++) {
        float4 x = v[i], p = a[i], q = b[i];
        s1 += x.x * p.x + x.y * p.y + x.z * p.z + x.w * p.w;
        s2 += x.x * q.x + x.y * q.y + x.z * q.z + x.w * q.w;
    }
    g_ssrc[idx] = s1;
    g_sdst[idx] = s2;
}

// ======== fused per-node aggregation: max -> denom -> weighted sum + bias+ELU
// one 64-thread block per dst node; no atomics.
__global__ void __launch_bounds__(64)
agg_kernel(const int* __restrict__ ptr, const int* __restrict__ csrc,
           const float* __restrict__ hp, const float* __restrict__ bias,
           float* __restrict__ out) {
    const int n = blockIdx.x;
    const int t = threadIdx.x;
    const int lane = t & 31, w = t >> 5;
    const int p0 = ptr[n];
    const int deg = ptr[n + 1] - p0;

    __shared__ float sm[2][8];
    __shared__ float sMax[8];
    __shared__ float sInv[8];
    __shared__ int se[64];

    // dst scores (broadcast load)
    float dh[8];
    {
        float4 d0 = ((const float4*)(g_sdst + (size_t)n * 8))[0];
        float4 d1 = ((const float4*)(g_sdst + (size_t)n * 8))[1];
        dh[0] = d0.x; dh[1] = d0.y; dh[2] = d0.z; dh[3] = d0.w;
        dh[4] = d1.x; dh[5] = d1.y; dh[6] = d1.z; dh[7] = d1.w;
    }

    // ---- phase A1: per-head max ----
    float mh[8];
#pragma unroll
    for (int h = 0; h < 8; h++) mh[h] = -1e30f;
    for (int i = t; i < deg; i += 64) {
        int s = csrc[p0 + i];
        float4 s0 = ((const float4*)(g_ssrc + (size_t)s * 8))[0];
        float4 s1 = ((const float4*)(g_ssrc + (size_t)s * 8))[1];
        float e[8];
        e[0] = s0.x + dh[0]; e[1] = s0.y + dh[1]; e[2] = s0.z + dh[2]; e[3] = s0.w + dh[3];
        e[4] = s1.x + dh[4]; e[5] = s1.y + dh[5]; e[6] = s1.z + dh[6]; e[7] = s1.w + dh[7];
#pragma unroll
        for (int h = 0; h < 8; h++) {
            float v = e[h] > 0.f ? e[h] : 0.2f * e[h];
            mh[h] = fmaxf(mh[h], v);
        }
    }
#pragma unroll
    for (int off = 16; off; off >>= 1)
#pragma unroll
        for (int h = 0; h < 8; h++)
            mh[h] = fmaxf(mh[h], __shfl_xor_sync(0xffffffffu, mh[h], off));
    if (lane == 0)
#pragma unroll
        for (int h = 0; h < 8; h++) sm[w][h] = mh[h];
    __syncthreads();
    float M[8];
#pragma unroll
    for (int h = 0; h < 8; h++) M[h] = fmaxf(sm[0][h], sm[1][h]);
    __syncthreads();

    // ---- phase A2: per-head denom ----
    float sumh[8];
#pragma unroll
    for (int h = 0; h < 8; h++) sumh[h] = 0.f;
    for (int i = t; i < deg; i += 64) {
        int s = csrc[p0 + i];
        float4 s0 = ((const float4*)(g_ssrc + (size_t)s * 8))[0];
        float4 s1 = ((const float4*)(g_ssrc + (size_t)s * 8))[1];
        float e[8];
        e[0] = s0.x + dh[0]; e[1] = s0.y + dh[1]; e[2] = s0.z + dh[2]; e[3] = s0.w + dh[3];
        e[4] = s1.x + dh[4]; e[5] = s1.y + dh[5]; e[6] = s1.z + dh[6]; e[7] = s1.w + dh[7];
#pragma unroll
        for (int h = 0; h < 8; h++) {
            float v = e[h] > 0.f ? e[h] : 0.2f * e[h];
            sumh[h] += expf(v - M[h]);
        }
    }
#pragma unroll
    for (int off = 16; off; off >>= 1)
#pragma unroll
        for (int h = 0; h < 8; h++)
            sumh[h] += __shfl_xor_sync(0xffffffffu, sumh[h], off);
    if (lane == 0)
#pragma unroll
        for (int h = 0; h < 8; h++) sm[w][h] = sumh[h];
    __syncthreads();
    if (t < 8) {
        sMax[t] = M[t];
        sInv[t] = 1.f / (sm[0][t] + sm[1][t]);
    }
    __syncthreads();

    // ---- phase B: weighted accumulation ----
    const int myh = t >> 3;
    const float mym = sMax[myh];
    const float myinv = sInv[myh];
    const float mysd = dh[myh];
    float4 acc = make_float4(0.f, 0.f, 0.f, 0.f);

    for (int c0 = 0; c0 < deg; c0 += 64) {
        int cnt = min(64, deg - c0);
        __syncthreads();
        if (t < cnt) se[t] = csrc[p0 + c0 + t];
        __syncthreads();
        for (int i = 0; i < cnt; i++) {
            int s = se[i];
            float alpha = 0.f;
            if ((lane & 7) == 0) {
                float e = g_ssrc[(size_t)s * 8 + myh] + mysd;
                e = e > 0.f ? e : 0.2f * e;
                alpha = expf(e - mym) * myinv;
            }
            alpha = __shfl_sync(0xffffffffu, alpha, lane & 24);
            float4 x = ((const float4*)(hp + (size_t)s * FDIM))[t];
            acc.x = fmaf(alpha, x.x, acc.x);
            acc.y = fmaf(alpha, x.y, acc.y);
            acc.z = fmaf(alpha, x.z, acc.z);
            acc.w = fmaf(alpha, x.w, acc.w);
        }
    }

    // bias + ELU, direct store
    float4 bv = ((const float4*)bias)[t];
    float v;
    v = acc.x + bv.x; acc.x = v > 0.f ? v : expm1f(v);
    v = acc.y + bv.y; acc.y = v > 0.f ? v : expm1f(v);
    v = acc.z + bv.z; acc.z = v > 0.f ? v : expm1f(v);
    v = acc.w + bv.w; acc.w = v > 0.f ? v : expm1f(v);
    ((float4*)(out + (size_t)n * FDIM))[t] = acc;
}

// -------- semantic attention fuse: scores -> softmax -> weighted sum ---------
__global__ void __launch_bounds__(128)
semfuse_kernel(const float* __restrict__ semW2) {
    int n = blockIdx.x;
    int t = threadIdx.x;  // 128
    __shared__ float red[4];
    __shared__ float w[3];
    float sloc[3];
    for (int p = 0; p < 3; p++) {
        float v = tanhf(g_hsem[((size_t)p * N_NODES + n) * 128 + t]) * semW2[t];
#pragma unroll
        for (int o = 16; o; o >>= 1) v += __shfl_down_sync(0xffffffffu, v, o);
        if ((t & 31) == 0) red[t >> 5] = v;
        __syncthreads();
        if (t == 0) sloc[p] = red[0] + red[1] + red[2] + red[3];
        __syncthreads();
    }
    if (t == 0) {
        float mx = fmaxf(sloc[0], fmaxf(sloc[1], sloc[2]));
        float e0 = expf(sloc[0] - mx), e1 = expf(sloc[1] - mx), e2 = expf(sloc[2] - mx);
        float inv = 1.f / (e0 + e1 + e2);
        w[0] = e0 * inv; w[1] = e1 * inv; w[2] = e2 * inv;
    }
    __syncthreads();
    for (int c = t; c < FDIM; c += 128) {
        float acc = 0.f;
#pragma unroll
        for (int p = 0; p < 3; p++)
            acc += w[p] * g_embs[((size_t)p * N_NODES + n) * FDIM + c];
        g_z[(size_t)n * FDIM + c] = acc;
    }
}

// -------- final 128->2 head --------------------------------------------------
__global__ void __launch_bounds__(128)
cls_final_kernel(const float* __restrict__ W2, const float* __restrict__ b2,
                 float* __restrict__ out) {
    int n = blockIdx.x;
    int t = threadIdx.x;  // 128
    float h = g_hcls[(size_t)n * 128 + t];
    float a0 = h * W2[t * 2 + 0];
    float a1 = h * W2[t * 2 + 1];
    __shared__ float r0[4], r1[4];
#pragma unroll
    for (int o = 16; o; o >>= 1) {
        a0 += __shfl_down_sync(0xffffffffu, a0, o);
        a1 += __shfl_down_sync(0xffffffffu, a1, o);
    }
    if ((t & 31) == 0) { r0[t >> 5] = a0; r1[t >> 5] = a1; }
    __syncthreads();
    if (t == 0) {
        out[n * 2 + 0] = r0[0] + r0[1] + r0[2] + r0[3] + b2[0];
        out[n * 2 + 1] = r1[0] + r1[1] + r1[2] + r1[3] + b2[1];
    }
}

// ---------------- host -------------------------------------------------------
extern "C" void kernel_launch(void* const* d_in, const int* in_sizes, int n_in,
                              void* d_out, int out_size) {
    const float* x       = (const float*)d_in[0];
    const int*   edges   = (const int*)d_in[1];
    const float* proj_W  = (const float*)d_in[2];
    const float* proj_b  = (const float*)d_in[3];
    const float* gat_W   = (const float*)d_in[4];
    const float* gat_asrc= (const float*)d_in[5];
    const float* gat_adst= (const float*)d_in[6];
    const float* gat_b   = (const float*)d_in[7];
    const float* sem_W1  = (const float*)d_in[8];
    const float* sem_b1  = (const float*)d_in[9];
    const float* sem_W2  = (const float*)d_in[10];
    const float* cls_W1  = (const float*)d_in[11];
    const float* cls_b1  = (const float*)d_in[12];
    const float* cls_W2  = (const float*)d_in[13];
    const float* cls_b2  = (const float*)d_in[14];
    float* out = (float*)d_out;

    float *p_h0, *p_h, *p_hp, *p_embs, *p_hsem, *p_z, *p_hcls;
    int *p_ptr, *p_csr;
    cudaGetSymbolAddress((void**)&p_h0,   g_h0);
    cudaGetSymbolAddress((void**)&p_h,    g_h);
    cudaGetSymbolAddress((void**)&p_hp,   g_hp);
    cudaGetSymbolAddress((void**)&p_embs, g_embs);
    cudaGetSymbolAddress((void**)&p_hsem, g_hsem);
    cudaGetSymbolAddress((void**)&p_z,    g_z);
    cudaGetSymbolAddress((void**)&p_hcls, g_hcls);
    cudaGetSymbolAddress((void**)&p_ptr,  g_ptr);
    cudaGetSymbolAddress((void**)&p_csr,  g_csr);

    // ---- CSR build (edges are constant across the forward) ----
    csr_zero_kernel<<<(3 * N_NODES + 255) / 256, 256>>>();
    dim3 ge((ET + 255) / 256, 3);
    csr_hist_kernel<<<ge, 256>>>(edges);
    csr_scan_kernel<<<3, 1024>>>();
    csr_scatter_kernel<<<ge, 256>>>(edges);

    const int M = N_NODES;
    dim3 gproj((M + 127) / 128, 2);
    gemm_tf32<1><<<gproj, 256>>>(x, proj_W, proj_b, p_h0, M, 128, 256);

    const int scoreGrid = (N_NODES * NHEAD + 255) / 256;

    for (int p = 0; p < 3; p++) {
        const int* ptr = p_ptr + (size_t)p * (N_NODES + 1);
        const int* csr = p_csr + (size_t)p * ET;
        for (int l = 0; l < 2; l++) {
            const float* W  = gat_W    + (size_t)(p * 2 + l) * 256 * 256;
            const float* as = gat_asrc + (size_t)(p * 2 + l) * NHEAD * DH;
            const float* ad = gat_adst + (size_t)(p * 2 + l) * NHEAD * DH;
            const float* gb = gat_b    + (size_t)(p * 2 + l) * 256;
            const float* hin = (l == 0) ? p_h0 : p_h;
            float* hout = (l == 0) ? p_h : (p_embs + (size_t)p * N_NODES * FDIM);

            gemm_tf32<0><<<gproj, 256>>>(hin, W, nullptr, p_hp, M, 256, 256);
            scores_kernel<<<scoreGrid, 256>>>(p_hp, as, ad);
            agg_kernel<<<N_NODES, 64>>>(ptr, csr, p_hp, gb, hout);
        }
    }

    // semantic attention
    dim3 gsem((3 * N_NODES + 127) / 128, 1);
    gemm_tf32<1><<<gsem, 256>>>(p_embs, sem_W1, sem_b1, p_hsem, 3 * N_NODES, 256, 128);
    semfuse_kernel<<<N_NODES, 128>>>(sem_W2);

    // classifier
    dim3 gcls((M + 127) / 128, 1);
    gemm_tf32<2><<<gcls, 256>>>(p_z, cls_W1, cls_b1, p_hcls, M, 256, 128);
    cls_final_kernel<<<N_NODES, 128>>>(cls_W2, cls_b2, out);
}

// round 9
// speedup vs baseline: 3.2489x; 1.2264x over previous
#include <cuda_runtime.h>
#include <cuda_bf16.h>
#include <math.h>
#include <stdint.h>

#define N_NODES 50000
#define EDGES   800000
#define ET      (EDGES + N_NODES)   // edges + self loops = 850000
#define NHEAD   8
#define DH      32
#define FDIM    256

// ---------------- scratch (device globals; no allocation allowed) ------------
__device__ float g_h0[N_NODES * FDIM];
__device__ float g_hbuf[3 * N_NODES * FDIM];   // per-metapath intermediate h
__device__ float g_hp[3 * N_NODES * FDIM];     // per-metapath projected feats
__device__ float g_embs[3 * N_NODES * FDIM];
__device__ float g_ssrc[3 * N_NODES * NHEAD];
__device__ float g_sdst[3 * N_NODES * NHEAD];
__device__ float g_hsem[3 * N_NODES * 128];
__device__ float g_z[N_NODES * FDIM];
__device__ float g_hcls[N_NODES * 128];

// CSR (built once per launch; edges constant)
__device__ int g_deg[3 * N_NODES];
__device__ int g_fill[3 * N_NODES];
__device__ int g_ptr[3 * (N_NODES + 1)];
__device__ int g_csr[3 * ET];

// ================= CSR build =================================================
__global__ void csr_zero_kernel() {
    int idx = blockIdx.x * blockDim.x + threadIdx.x;
    if (idx < 3 * N_NODES) g_deg[idx] = 0;
}

__global__ void csr_hist_kernel(const int* __restrict__ edges) {
    int idx = blockIdx.x * blockDim.x + threadIdx.x;
    int p = blockIdx.y;
    if (idx >= ET) return;
    int d = (idx < EDGES) ? edges[(size_t)p * 2 * EDGES + EDGES + idx] : idx - EDGES;
    atomicAdd(&g_deg[p * N_NODES + d], 1);
}

// one block per metapath; 1024 threads; chunked warp-scan
__global__ void __launch_bounds__(1024) csr_scan_kernel() {
    int p = blockIdx.x;
    int tid = threadIdx.x;
    int lane = tid & 31, wid = tid >> 5;
    __shared__ int swarp[32];
    __shared__ int s_carry;
    if (tid == 0) s_carry = 0;
    __syncthreads();
    for (int base = 0; base < N_NODES; base += 1024) {
        int i = base + tid;
        int v = (i < N_NODES) ? g_deg[p * N_NODES + i] : 0;
        int incl = v;
#pragma unroll
        for (int off = 1; off < 32; off <<= 1) {
            int t = __shfl_up_sync(0xffffffffu, incl, off);
            if (lane >= off) incl += t;
        }
        if (lane == 31) swarp[wid] = incl;
        __syncthreads();
        if (wid == 0) {
            int s = swarp[lane];
#pragma unroll
            for (int off = 1; off < 32; off <<= 1) {
                int t = __shfl_up_sync(0xffffffffu, s, off);
                if (lane >= off) s += t;
            }
            swarp[lane] = s;
        }
        __syncthreads();
        int woff = (wid > 0) ? swarp[wid - 1] : 0;
        incl += woff;
        int excl = incl - v;
        int carry = s_carry;
        if (i < N_NODES) {
            g_ptr[p * (N_NODES + 1) + i] = carry + excl;
            g_fill[p * N_NODES + i] = carry + excl;
        }
        int total = swarp[31];
        __syncthreads();
        if (tid == 0) s_carry = carry + total;
        __syncthreads();
    }
    if (tid == 0) g_ptr[p * (N_NODES + 1) + N_NODES] = s_carry;
}

__global__ void csr_scatter_kernel(const int* __restrict__ edges) {
    int idx = blockIdx.x * blockDim.x + threadIdx.x;
    int p = blockIdx.y;
    if (idx >= ET) return;
    int s, d;
    if (idx < EDGES) {
        s = edges[(size_t)p * 2 * EDGES + idx];
        d = edges[(size_t)p * 2 * EDGES + EDGES + idx];
    } else {
        s = idx - EDGES; d = s;
    }
    int pos = atomicAdd(&g_fill[p * N_NODES + d], 1);
    g_csr[(size_t)p * ET + pos] = s;
}

// ================= tf32 tensor-core GEMM =====================================
__device__ __forceinline__ uint32_t f2tf32(float f) {
    uint32_t r;
    asm("cvt.rna.tf32.f32 %0, %1;" : "=r"(r) : "f"(f));
    return r;
}

__device__ __forceinline__ void mma_tf32(float* cc,
                                         uint32_t a0, uint32_t a1, uint32_t a2, uint32_t a3,
                                         uint32_t b0, uint32_t b1) {
    asm volatile(
        "mma.sync.aligned.m16n8k8.row.col.f32.tf32.tf32.f32 "
        "{%0,%1,%2,%3}, {%4,%5,%6,%7}, {%8,%9}, {%0,%1,%2,%3};"
        : "+f"(cc[0]), "+f"(cc[1]), "+f"(cc[2]), "+f"(cc[3])
        : "r"(a0), "r"(a1), "r"(a2), "r"(a3), "r"(b0), "r"(b1));
}

template <int EPI>  // 0 none, 1 +bias, 2 +bias+relu
__global__ void __launch_bounds__(256)
gemm_tf32(const float* __restrict__ A, const float* __restrict__ B,
          const float* __restrict__ bias, float* __restrict__ C,
          int M, int K, int Nc) {
    __shared__ uint32_t As[128][36];
    __shared__ uint32_t Bs[32][132];

    const int bm = blockIdx.x * 128;
    const int bn = blockIdx.y * 128;
    const int tid = threadIdx.x;
    const int lane = tid & 31;
    const int warp = tid >> 5;
    const int wm = (warp & 1) * 64;
    const int wn = (warp >> 1) * 32;
    const int gq = lane >> 2;
    const int cq = lane & 3;

    const int ar = tid >> 3;
    const int ac = (tid & 7) * 4;
    const int br = tid >> 5;
    const int bc = (tid & 31) * 4;

    float4 ra[4], rb[4];
#pragma unroll
    for (int i = 0; i < 4; i++) {
        int row = ar + 32 * i;
        ra[i] = (bm + row < M) ? *(const float4*)(A + (size_t)(bm + row) * K + ac)
                               : make_float4(0.f, 0.f, 0.f, 0.f);
        rb[i] = *(const float4*)(B + (size_t)(br + 8 * i) * Nc + bn + bc);
    }
#pragma unroll
    for (int i = 0; i < 4; i++) {
        int row = ar + 32 * i;
        As[row][ac + 0] = f2tf32(ra[i].x); As[row][ac + 1] = f2tf32(ra[i].y);
        As[row][ac + 2] = f2tf32(ra[i].z); As[row][ac + 3] = f2tf32(ra[i].w);
        int kr = br + 8 * i;
        Bs[kr][bc + 0] = f2tf32(rb[i].x); Bs[kr][bc + 1] = f2tf32(rb[i].y);
        Bs[kr][bc + 2] = f2tf32(rb[i].z); Bs[kr][bc + 3] = f2tf32(rb[i].w);
    }
    __syncthreads();

    float acc[4][4][4];
#pragma unroll
    for (int i = 0; i < 4; i++)
#pragma unroll
        for (int j = 0; j < 4; j++)
#pragma unroll
            for (int q = 0; q < 4; q++) acc[i][j][q] = 0.f;

#define COMPUTE_TILE()                                                          \
    {                                                                           \
        _Pragma("unroll")                                                       \
        for (int ks = 0; ks < 4; ks++) {                                        \
            const int kb = ks * 8;                                              \
            uint32_t af[4][4], bf[4][2];                                        \
            _Pragma("unroll")                                                   \
            for (int i = 0; i < 4; i++) {                                       \
                int r0 = wm + i * 16 + gq;                                      \
                af[i][0] = As[r0][kb + cq];                                     \
                af[i][1] = As[r0 + 8][kb + cq];                                 \
                af[i][2] = As[r0][kb + cq + 4];                                 \
                af[i][3] = As[r0 + 8][kb + cq + 4];                             \
            }                                                                   \
            _Pragma("unroll")                                                   \
            for (int j = 0; j < 4; j++) {                                       \
                int col = wn + j * 8 + gq;                                      \
                bf[j][0] = Bs[kb + cq][col];                                    \
                bf[j][1] = Bs[kb + cq + 4][col];                                \
            }                                                                   \
            _Pragma("unroll")                                                   \
            for (int i = 0; i < 4; i++)                                         \
                _Pragma("unroll")                                               \
                for (int j = 0; j < 4; j++)                                     \
                    mma_tf32(acc[i][j], af[i][0], af[i][1], af[i][2], af[i][3], \
                             bf[j][0], bf[j][1]);                               \
        }                                                                       \
    }

    for (int k0 = 32; k0 < K; k0 += 32) {
#pragma unroll
        for (int i = 0; i < 4; i++) {
            int row = ar + 32 * i;
            ra[i] = (bm + row < M) ? *(const float4*)(A + (size_t)(bm + row) * K + k0 + ac)
                                   : make_float4(0.f, 0.f, 0.f, 0.f);
            rb[i] = *(const float4*)(B + (size_t)(k0 + br + 8 * i) * Nc + bn + bc);
        }
        COMPUTE_TILE();
        __syncthreads();
#pragma unroll
        for (int i = 0; i < 4; i++) {
            int row = ar + 32 * i;
            As[row][ac + 0] = f2tf32(ra[i].x); As[row][ac + 1] = f2tf32(ra[i].y);
            As[row][ac + 2] = f2tf32(ra[i].z); As[row][ac + 3] = f2tf32(ra[i].w);
            int kr = br + 8 * i;
            Bs[kr][bc + 0] = f2tf32(rb[i].x); Bs[kr][bc + 1] = f2tf32(rb[i].y);
            Bs[kr][bc + 2] = f2tf32(rb[i].z); Bs[kr][bc + 3] = f2tf32(rb[i].w);
        }
        __syncthreads();
    }
    COMPUTE_TILE();
#undef COMPUTE_TILE

#pragma unroll
    for (int i = 0; i < 4; i++) {
        int r0 = bm + wm + i * 16 + gq;
        int r1 = r0 + 8;
#pragma unroll
        for (int j = 0; j < 4; j++) {
            int col = bn + wn + j * 8 + 2 * cq;
            float2 v0 = make_float2(acc[i][j][0], acc[i][j][1]);
            float2 v1 = make_float2(acc[i][j][2], acc[i][j][3]);
            if (EPI >= 1) {
                float2 bv = *(const float2*)(bias + col);
                v0.x += bv.x; v0.y += bv.y; v1.x += bv.x; v1.y += bv.y;
            }
            if (EPI == 2) {
                v0.x = fmaxf(v0.x, 0.f); v0.y = fmaxf(v0.y, 0.f);
                v1.x = fmaxf(v1.x, 0.f); v1.y = fmaxf(v1.y, 0.f);
            }
            if (r0 < M) *(float2*)(C + (size_t)r0 * Nc + col) = v0;
            if (r1 < M) *(float2*)(C + (size_t)r1 * Nc + col) = v1;
        }
    }
}

// -------- per-(node,head) attention logits -----------------------------------
__global__ void scores_kernel(const float* __restrict__ hp,
                              const float* __restrict__ asrc,
                              const float* __restrict__ adst,
                              float* __restrict__ ssrc,
                              float* __restrict__ sdst) {
    int idx = blockIdx.x * blockDim.x + threadIdx.x;
    if (idx >= N_NODES * NHEAD) return;
    int n = idx >> 3, h = idx & 7;
    const float4* v = (const float4*)(hp + (size_t)n * FDIM + h * DH);
    const float4* a = (const float4*)(asrc + h * DH);
    const float4* b = (const float4*)(adst + h * DH);
    float s1 = 0.f, s2 = 0.f;
#pragma unroll
    for (int i = 0; i < 8; i++) {
        float4 x = v[i], p = a[i], q = b[i];
        s1 += x.x * p.x + x.y * p.y + x.z * p.z + x.w * p.w;
        s2 += x.x * q.x + x.y * q.y + x.z * q.z + x.w * q.w;
    }
    ssrc[idx] = s1;
    sdst[idx] = s2;
}

// ======== single-pass aggregation ============================================
// alpha = exp(e)/sum(exp(e)) computed WITHOUT max subtraction (mathematically
// identical; logits are O(1) here so no overflow). One pass over the edge list:
// accumulate sum(exp(e)*hp[src]) and sum(exp(e)); divide; +bias; ELU.
// 64 threads per dst node: 8 threads/head, float4 per thread.
__global__ void __launch_bounds__(64)
agg_kernel(const int* __restrict__ ptr, const int* __restrict__ csrc,
           const float* __restrict__ hp,
           const float* __restrict__ ssrc, const float* __restrict__ sdst,
           const float* __restrict__ bias, float* __restrict__ out) {
    const int n = blockIdx.x;
    const int t = threadIdx.x;
    const int lane = t & 31;
    const int p0 = ptr[n];
    const int deg = ptr[n + 1] - p0;
    __shared__ int se[64];

    const int myh = t >> 3;
    const float mysd = sdst[(size_t)n * 8 + myh];
    const bool leader = (lane & 7) == 0;

    float4 acc = make_float4(0.f, 0.f, 0.f, 0.f);
    float wsum = 0.f;

    for (int c0 = 0; c0 < deg; c0 += 64) {
        int cnt = min(64, deg - c0);
        __syncthreads();
        if (t < cnt) se[t] = csrc[p0 + c0 + t];
        __syncthreads();
        for (int i = 0; i < cnt; i++) {
            int s = se[i];
            float w = 0.f;
            if (leader) {
                float e = ssrc[(size_t)s * 8 + myh] + mysd;
                e = e > 0.f ? e : 0.2f * e;
                w = expf(e);
                wsum += w;
            }
            w = __shfl_sync(0xffffffffu, w, lane & 24);
            float4 x = ((const float4*)(hp + (size_t)s * FDIM))[t];
            acc.x = fmaf(w, x.x, acc.x);
            acc.y = fmaf(w, x.y, acc.y);
            acc.z = fmaf(w, x.z, acc.z);
            acc.w = fmaf(w, x.w, acc.w);
        }
    }

    float wtot = __shfl_sync(0xffffffffu, wsum, lane & 24);
    float inv = 1.f / wtot;

    float4 bv = ((const float4*)bias)[t];
    float v;
    v = fmaf(acc.x, inv, bv.x); acc.x = v > 0.f ? v : expm1f(v);
    v = fmaf(acc.y, inv, bv.y); acc.y = v > 0.f ? v : expm1f(v);
    v = fmaf(acc.z, inv, bv.z); acc.z = v > 0.f ? v : expm1f(v);
    v = fmaf(acc.w, inv, bv.w); acc.w = v > 0.f ? v : expm1f(v);
    ((float4*)(out + (size_t)n * FDIM))[t] = acc;
}

// -------- semantic attention fuse: scores -> softmax -> weighted sum ---------
__global__ void __launch_bounds__(128)
semfuse_kernel(const float* __restrict__ semW2) {
    int n = blockIdx.x;
    int t = threadIdx.x;  // 128
    __shared__ float red[4];
    __shared__ float w[3];
    float sloc[3];
    for (int p = 0; p < 3; p++) {
        float v = tanhf(g_hsem[((size_t)p * N_NODES + n) * 128 + t]) * semW2[t];
#pragma unroll
        for (int o = 16; o; o >>= 1) v += __shfl_down_sync(0xffffffffu, v, o);
        if ((t & 31) == 0) red[t >> 5] = v;
        __syncthreads();
        if (t == 0) sloc[p] = red[0] + red[1] + red[2] + red[3];
        __syncthreads();
    }
    if (t == 0) {
        float mx = fmaxf(sloc[0], fmaxf(sloc[1], sloc[2]));
        float e0 = expf(sloc[0] - mx), e1 = expf(sloc[1] - mx), e2 = expf(sloc[2] - mx);
        float inv = 1.f / (e0 + e1 + e2);
        w[0] = e0 * inv; w[1] = e1 * inv; w[2] = e2 * inv;
    }
    __syncthreads();
    for (int c = t; c < FDIM; c += 128) {
        float acc = 0.f;
#pragma unroll
        for (int p = 0; p < 3; p++)
            acc += w[p] * g_embs[((size_t)p * N_NODES + n) * FDIM + c];
        g_z[(size_t)n * FDIM + c] = acc;
    }
}

// -------- final 128->2 head --------------------------------------------------
__global__ void __launch_bounds__(128)
cls_final_kernel(const float* __restrict__ W2, const float* __restrict__ b2,
                 float* __restrict__ out) {
    int n = blockIdx.x;
    int t = threadIdx.x;  // 128
    float h = g_hcls[(size_t)n * 128 + t];
    float a0 = h * W2[t * 2 + 0];
    float a1 = h * W2[t * 2 + 1];
    __shared__ float r0[4], r1[4];
#pragma unroll
    for (int o = 16; o; o >>= 1) {
        a0 += __shfl_down_sync(0xffffffffu, a0, o);
        a1 += __shfl_down_sync(0xffffffffu, a1, o);
    }
    if ((t & 31) == 0) { r0[t >> 5] = a0; r1[t >> 5] = a1; }
    __syncthreads();
    if (t == 0) {
        out[n * 2 + 0] = r0[0] + r0[1] + r0[2] + r0[3] + b2[0];
        out[n * 2 + 1] = r1[0] + r1[1] + r1[2] + r1[3] + b2[1];
    }
}

// ---------------- host -------------------------------------------------------
extern "C" void kernel_launch(void* const* d_in, const int* in_sizes, int n_in,
                              void* d_out, int out_size) {
    const float* x       = (const float*)d_in[0];
    const int*   edges   = (const int*)d_in[1];
    const float* proj_W  = (const float*)d_in[2];
    const float* proj_b  = (const float*)d_in[3];
    const float* gat_W   = (const float*)d_in[4];
    const float* gat_asrc= (const float*)d_in[5];
    const float* gat_adst= (const float*)d_in[6];
    const float* gat_b   = (const float*)d_in[7];
    const float* sem_W1  = (const float*)d_in[8];
    const float* sem_b1  = (const float*)d_in[9];
    const float* sem_W2  = (const float*)d_in[10];
    const float* cls_W1  = (const float*)d_in[11];
    const float* cls_b1  = (const float*)d_in[12];
    const float* cls_W2  = (const float*)d_in[13];
    const float* cls_b2  = (const float*)d_in[14];
    float* out = (float*)d_out;

    float *p_h0, *p_hbuf, *p_hp, *p_embs, *p_hsem, *p_z, *p_hcls, *p_ssrc, *p_sdst;
    int *p_ptr, *p_csr;
    cudaGetSymbolAddress((void**)&p_h0,   g_h0);
    cudaGetSymbolAddress((void**)&p_hbuf, g_hbuf);
    cudaGetSymbolAddress((void**)&p_hp,   g_hp);
    cudaGetSymbolAddress((void**)&p_embs, g_embs);
    cudaGetSymbolAddress((void**)&p_hsem, g_hsem);
    cudaGetSymbolAddress((void**)&p_z,    g_z);
    cudaGetSymbolAddress((void**)&p_hcls, g_hcls);
    cudaGetSymbolAddress((void**)&p_ssrc, g_ssrc);
    cudaGetSymbolAddress((void**)&p_sdst, g_sdst);
    cudaGetSymbolAddress((void**)&p_ptr,  g_ptr);
    cudaGetSymbolAddress((void**)&p_csr,  g_csr);

    // streams/events created ONCE, outside graph capture (first call is the
    // uncaptured correctness run). Reused on the capture call.
    static cudaStream_t st1 = nullptr, st2 = nullptr;
    static cudaEvent_t ev0, ev1, ev2, ev3, ev4;
    if (st1 == nullptr) {
        cudaStreamCreateWithFlags(&st1, cudaStreamNonBlocking);
        cudaStreamCreateWithFlags(&st2, cudaStreamNonBlocking);
        cudaEventCreateWithFlags(&ev0, cudaEventDisableTiming);
        cudaEventCreateWithFlags(&ev1, cudaEventDisableTiming);
        cudaEventCreateWithFlags(&ev2, cudaEventDisableTiming);
        cudaEventCreateWithFlags(&ev3, cudaEventDisableTiming);
        cudaEventCreateWithFlags(&ev4, cudaEventDisableTiming);
    }

    const int M = N_NODES;
    dim3 gproj((M + 127) / 128, 2);
    const int scoreGrid = (N_NODES * NHEAD + 255) / 256;

    // ---- fork: proj GEMM on st1, CSR build on main ----
    cudaEventRecord(ev0, 0);
    cudaStreamWaitEvent(st1, ev0, 0);
    gemm_tf32<1><<<gproj, 256, 0, st1>>>(x, proj_W, proj_b, p_h0, M, 128, 256);
    cudaEventRecord(ev1, st1);

    csr_zero_kernel<<<(3 * N_NODES + 255) / 256, 256>>>();
    dim3 ge((ET + 255) / 256, 3);
    csr_hist_kernel<<<ge, 256>>>(edges);
    csr_scan_kernel<<<3, 1024>>>();
    csr_scatter_kernel<<<ge, 256>>>(edges);

    cudaStreamWaitEvent(0, ev1, 0);
    cudaEventRecord(ev2, 0);                 // CSR + h0 both ready
    cudaStreamWaitEvent(st1, ev2, 0);
    cudaStreamWaitEvent(st2, ev2, 0);

    // ---- 3 independent meta-path chains, one per stream ----
    cudaStream_t chains[3] = { (cudaStream_t)0, st1, st2 };
    for (int p = 0; p < 3; p++) {
        cudaStream_t s = chains[p];
        const int* ptr = p_ptr + (size_t)p * (N_NODES + 1);
        const int* csr = p_csr + (size_t)p * ET;
        float* hp_p  = p_hp   + (size_t)p * N_NODES * FDIM;
        float* h_p   = p_hbuf + (size_t)p * N_NODES * FDIM;
        float* ss_p  = p_ssrc + (size_t)p * N_NODES * NHEAD;
        float* sd_p  = p_sdst + (size_t)p * N_NODES * NHEAD;
        for (int l = 0; l < 2; l++) {
            const float* W  = gat_W    + (size_t)(p * 2 + l) * 256 * 256;
            const float* as = gat_asrc + (size_t)(p * 2 + l) * NHEAD * DH;
            const float* ad = gat_adst + (size_t)(p * 2 + l) * NHEAD * DH;
            const float* gb = gat_b    + (size_t)(p * 2 + l) * 256;
            const float* hin = (l == 0) ? p_h0 : h_p;
            float* hout = (l == 0) ? h_p : (p_embs + (size_t)p * N_NODES * FDIM);

            gemm_tf32<0><<<gproj, 256, 0, s>>>(hin, W, nullptr, hp_p, M, 256, 256);
            scores_kernel<<<scoreGrid, 256, 0, s>>>(hp_p, as, ad, ss_p, sd_p);
            agg_kernel<<<N_NODES, 64, 0, s>>>(ptr, csr, hp_p, ss_p, sd_p, gb, hout);
        }
    }

    // ---- join ----
    cudaEventRecord(ev3, st1);
    cudaEventRecord(ev4, st2);
    cudaStreamWaitEvent(0, ev3, 0);
    cudaStreamWaitEvent(0, ev4, 0);

    // semantic attention
    dim3 gsem((3 * N_NODES + 127) / 128, 1);
    gemm_tf32<1><<<gsem, 256>>>(p_embs, sem_W1, sem_b1, p_hsem, 3 * N_NODES, 256, 128);
    semfuse_kernel<<<N_NODES, 128>>>(sem_W2);

    // classifier
    dim3 gcls((M + 127) / 128, 1);
    gemm_tf32<2><<<gcls, 256>>>(p_z, cls_W1, cls_b1, p_hcls, M, 256, 128);
    cls_final_kernel<<<N_NODES, 128>>>(cls_W2, cls_b2, out);
}